// round 12
// baseline (speedup 1.0000x reference)
#include <cuda_runtime.h>
#include <cuda_bf16.h>
#include <cstdint>

#define CH     512
#define HW     4096
#define SCALE  (1.0e6f / 33554432.0f)
#define NGEMM  272    // 136 upper-tri 32x32 tiles x splitK 2
#define NSCTA  512
#define NCTA   (NGEMM + NSCTA)
#define NUNITS 4096   // (row r: 0..511) x (eighth of j: 32 j's)

__device__ __align__(16) __nv_bfloat16 g_feats[CH * HW];  // 4 MB bf16 feats
__device__ __align__(16) float g_G[CH * CH];              // gram (scaled 1/2^20)
__device__ __align__(16) float g_S[CH * CH];              // S (atomic partial sums)
__device__ float g_T2acc;                                 // sum T^2 (reset per launch)
__device__ unsigned int g_work;                           // ticket ctr (reset per launch)
__device__ unsigned int g_barA;   // monotonic, +NCTA per launch
__device__ unsigned int g_barB;   // monotonic, +NCTA per launch

// ---------------------------------------------------------------------------
__device__ __forceinline__ uint32_t smem_u32(const void* p) {
    return static_cast<uint32_t>(__cvta_generic_to_shared(p));
}
__device__ __forceinline__ void cp_async16(uint32_t dst, const void* src) {
    asm volatile("cp.async.cg.shared.global [%0], [%1], 16;\n" :: "r"(dst), "l"(src));
}
template <int N>
__device__ __forceinline__ void cp_wait() {
    asm volatile("cp.async.wait_group %0;\n" :: "n"(N) : "memory");
}
__device__ __forceinline__ void cp_commit() {
    asm volatile("cp.async.commit_group;\n" ::: "memory");
}
__device__ __forceinline__ void ldm_x4(uint32_t* d, uint32_t addr) {
    asm volatile("ldmatrix.sync.aligned.m8n8.x4.shared.b16 {%0,%1,%2,%3}, [%4];"
                 : "=r"(d[0]), "=r"(d[1]), "=r"(d[2]), "=r"(d[3]) : "r"(addr));
}
__device__ __forceinline__ void ldm_x2(uint32_t* d, uint32_t addr) {
    asm volatile("ldmatrix.sync.aligned.m8n8.x2.shared.b16 {%0,%1}, [%2];"
                 : "=r"(d[0]), "=r"(d[1]) : "r"(addr));
}
__device__ __forceinline__ void mma_bf16(float* c, const uint32_t* a, uint32_t b0, uint32_t b1) {
    asm volatile("mma.sync.aligned.m16n8k16.row.col.f32.bf16.bf16.f32 "
                 "{%0,%1,%2,%3},{%4,%5,%6,%7},{%8,%9},{%0,%1,%2,%3};"
                 : "+f"(c[0]), "+f"(c[1]), "+f"(c[2]), "+f"(c[3])
                 : "r"(a[0]), "r"(a[1]), "r"(a[2]), "r"(a[3]), "r"(b0), "r"(b1));
}
__device__ __forceinline__ void spin_to(unsigned int* ctr, unsigned tgt) {
    unsigned cur;
    do {
        __nanosleep(64);
        asm volatile("ld.acquire.gpu.u32 %0, [%1];" : "=r"(cur) : "l"(ctr));
    } while (cur < tgt);
}

// smem 24640B: GEMM ring 3 slots x 8KB (A @0, B @4096 per slot, XOR swizzle)
//              tk_slot int @24576, red[8] @24580  (outside the GEMM ring)
__global__ void __launch_bounds__(256, 8) k_all(const float* __restrict__ x,
                                                const float* __restrict__ target,
                                                float* __restrict__ out) {
    __shared__ __align__(16) char sm[24640];
    int*   tk_slot = reinterpret_cast<int*>(sm + 24576);
    float* red     = reinterpret_cast<float*>(sm + 24580);
    const int t = threadIdx.x;
    const int w = t >> 5, l = t & 31;
    const int bid = blockIdx.x;

    // ============ Phase 1: convert x -> bf16 (all CTAs), zero G & S ============
    const int gi = bid * 256 + t;
    for (int idx = gi; idx < 524288; idx += NCTA * 256) {
        float4 v = reinterpret_cast<const float4*>(x)[idx];
        __nv_bfloat162 p0, p1;
        p0.x = __float2bfloat16(v.x); p0.y = __float2bfloat16(v.y);
        p1.x = __float2bfloat16(v.z); p1.y = __float2bfloat16(v.w);
        uint2 pk;
        pk.x = *reinterpret_cast<uint32_t*>(&p0);
        pk.y = *reinterpret_cast<uint32_t*>(&p1);
        reinterpret_cast<uint2*>(g_feats)[idx] = pk;
    }
    if (gi < 65536)
        reinterpret_cast<float4*>(g_G)[gi] = make_float4(0.f, 0.f, 0.f, 0.f);
    else if (gi < 131072)
        reinterpret_cast<float4*>(g_S)[gi - 65536] = make_float4(0.f, 0.f, 0.f, 0.f);
    if (gi == 0) out[0] = 0.0f;

    __threadfence();
    __syncthreads();
    unsigned tgtA = 0;
    if (t == 0) {
        unsigned old = atomicAdd(&g_barA, 1u);
        tgtA = old - (old % NCTA) + NCTA;
        if (bid < NGEMM) spin_to(&g_barA, tgtA);   // GEMM needs feats now
    }
    bool needA = (bid >= NGEMM);                   // S CTAs defer to first flush

    if (bid < NGEMM) {
        // ====== GEMM: 32x32 upper-tri tiles, splitK 2 (R11-proven, 32 regs) ======
        __syncthreads();
        const int tile = bid % 136;
        const int kz   = (bid / 136) * 2048;
        int rem = tile, bi = 0;
        while (rem >= 16 - bi) { rem -= 16 - bi; bi++; }
        const int bj = bi + rem;
        const int m0 = bi * 32, n0 = bj * 32;

        const int wm = (w >> 2) * 16;    // 0,16
        const int wn = (w & 3) * 8;      // 0,8,16,24

        float acc[4];
        acc[0] = acc[1] = acc[2] = acc[3] = 0.f;

        const int lrow = l & 15;
        const int lkh2 = (l >> 4) * 16;          // byte offset for A k-half
        const int rb   = wn + (l & 7);           // B row
        const int cbB0 = ((l >> 3) & 1) * 16;    // B k-half bytes
        const uint32_t smb = smem_u32(sm);

        const int srow = t >> 3;                 // 0..31
        const int sc16 = (t & 7) * 16;           // byte col
        const uint32_t sdst = (uint32_t)(((srow * 128 + sc16) ^ ((srow & 7) << 4)));

        #define GLOAD(KS, SL) do {                                           \
            const int kb_ = kz + (KS) * 64;                                  \
            cp_async16(smb + (SL) * 8192 + sdst,                             \
                       &g_feats[(m0 + srow) * HW + kb_ + (t & 7) * 8]);      \
            cp_async16(smb + (SL) * 8192 + 4096 + sdst,                      \
                       &g_feats[(n0 + srow) * HW + kb_ + (t & 7) * 8]);      \
            cp_commit();                                                     \
        } while (0)

        GLOAD(0, 0);
        GLOAD(1, 1);
        for (int ks = 0; ks < 32; ks++) {
            if (ks < 31) cp_wait<1>(); else cp_wait<0>();
            __syncthreads();
            if (ks < 30) GLOAD(ks + 2, (ks + 2) % 3);

            const uint32_t slot = smb + (ks % 3) * 8192;
            #pragma unroll
            for (int k16 = 0; k16 < 4; k16++) {
                uint32_t afr[4], bfr[2];
                const int ra = wm + lrow;
                const int cbA = k16 * 32 + lkh2;
                ldm_x4(afr, slot + (uint32_t)((ra * 128 + cbA) ^ ((ra & 7) << 4)));
                const int cbB = k16 * 32 + cbB0;
                ldm_x2(bfr, slot + 4096 + (uint32_t)((rb * 128 + cbB) ^ ((rb & 7) << 4)));
                mma_bf16(acc, afr, bfr[0], bfr[1]);
            }
        }
        #undef GLOAD

        const float s = 1.0f / 1048576.0f;
        const int g2 = l >> 2, cc = (l & 3) * 2;
        const bool mirror = (bi != bj);
        {
            const int row = m0 + wm + g2;
            const int col = n0 + wn + cc;
            const float v0 = acc[0] * s, v1 = acc[1] * s;
            const float v2 = acc[2] * s, v3 = acc[3] * s;
            atomicAdd(&g_G[row * CH + col],           v0);
            atomicAdd(&g_G[row * CH + col + 1],       v1);
            atomicAdd(&g_G[(row + 8) * CH + col],     v2);
            atomicAdd(&g_G[(row + 8) * CH + col + 1], v3);
            if (mirror) {
                atomicAdd(&g_G[col * CH + row],           v0);
                atomicAdd(&g_G[(col + 1) * CH + row],     v1);
                atomicAdd(&g_G[col * CH + row + 8],       v2);
                atomicAdd(&g_G[(col + 1) * CH + row + 8], v3);
            }
        }
        __threadfence();
        __syncthreads();
    }

    // ====== Work-stealing S-stream: pure-LDG gather, no smem, no inner syncs ======
    float T2a = 0.f, T2b = 0.f;

    while (true) {
        if (t == 0) *tk_slot = (int)atomicAdd(&g_work, 1u);
        __syncthreads();
        const int tk = *tk_slot;
        __syncthreads();
        if (tk >= NUNITS) break;

        const int r    = tk >> 3;
        const int jb0  = (tk & 7) * 32;
        const int base = (t - r) & 511;
        float Slo = 0.f, Shi = 0.f;

        #pragma unroll 1
        for (int jb = jb0; jb < jb0 + 32; jb += 8) {
            float v[8];
            #pragma unroll
            for (int u = 0; u < 8; u++) {
                const int j  = jb + u;
                const int i  = (r - j) & 511;
                const int kk = (base + j) & 511;
                v[u] = __ldg(&target[(i << 16) + (j << 8) + (kk & 255)]);
            }
            #pragma unroll
            for (int u = 0; u < 8; u++) {
                const int kk = (base + jb + u) & 511;
                if (u & 1) T2b = fmaf(v[u], v[u], T2b);
                else       T2a = fmaf(v[u], v[u], T2a);
                if (kk >> 8) Shi += v[u]; else Slo += v[u];
            }
        }

        if (needA) {                  // g_S zeroing must be done before 1st flush
            if (t == 0) spin_to(&g_barA, tgtA);
            __syncthreads();
            needA = false;
        }
        atomicAdd(&g_S[(r << 9) + t],       Slo);
        atomicAdd(&g_S[(r << 9) + 256 + t], Shi);
    }

    // flush T2 (block reduce, one atomic per CTA)
    float T2 = T2a + T2b;
    #pragma unroll
    for (int o = 16; o > 0; o >>= 1)
        T2 += __shfl_xor_sync(0xFFFFFFFFu, T2, o);
    if (l == 0) red[w] = T2;
    __syncthreads();
    if (t == 0) {
        float z = 0.f;
        #pragma unroll
        for (int ww = 0; ww < 8; ww++) z += red[ww];
        atomicAdd(&g_T2acc, z);
    }

    // ====== full barrier, then combine ======
    __threadfence();
    __syncthreads();
    if (t == 0) {
        unsigned old = atomicAdd(&g_barB, 1u);
        unsigned tgt = old - (old % NCTA) + NCTA;
        if (bid == 0 || bid >= NGEMM) spin_to(&g_barB, tgt);
    }
    if (bid > 0 && bid < NGEMM) return;       // arrived; no post-work
    __syncthreads();

    if (bid == 0) {
        if (t == 0) {
            atomicAdd(out, g_T2acc * SCALE);
            g_T2acc = 0.0f;                   // reset per-launch state
            g_work  = 0u;
        }
        return;
    }

    // combine row r = bid - NGEMM
    const int r = bid - NGEMM;
    const float Gl = g_G[(r << 9) + t];
    const float Gh = g_G[(r << 9) + t + 256];
    const float Sl = g_S[(r << 9) + t];
    const float Sh = g_S[(r << 9) + t + 256];
    const int d1 = (r - t) & 511;
    const int d2 = (r - t - 256) & 511;
    const float m1 = (float)((d1 <= 256) ? 256 - d1 : d1 - 256);
    const float m2 = (float)((d2 <= 256) ? 256 - d2 : d2 - 256);
    float term = fmaf(m1 * Gl, Gl, -2.0f * Gl * Sl)
               + fmaf(m2 * Gh, Gh, -2.0f * Gh * Sh);

    #pragma unroll
    for (int o = 16; o > 0; o >>= 1)
        term += __shfl_xor_sync(0xFFFFFFFFu, term, o);
    if (l == 0) red[w] = term;
    __syncthreads();
    if (t == 0) {
        float z = 0.f;
        #pragma unroll
        for (int ww = 0; ww < 8; ww++) z += red[ww];
        atomicAdd(out, z * SCALE);
    }
}

// ---------------------------------------------------------------------------
extern "C" void kernel_launch(void* const* d_in, const int* in_sizes, int n_in,
                              void* d_out, int out_size) {
    const float* x      = (const float*)d_in[0];   // (1,512,64,64) fp32
    const float* target = (const float*)d_in[1];   // (512,256,256) fp32
    float* out = (float*)d_out;

    k_all<<<NCTA, 256>>>(x, target, out);
}